// round 3
// baseline (speedup 1.0000x reference)
#include <cuda_runtime.h>
#include <math.h>

#define BB 2
#define CC 64
#define HH 64
#define WW 64
#define LL 4096
#define MM (BB*LL)          // 8192 tokens
#define DIN 128             // D_INNER
#define DST 64              // D_STATE
#define DTR 4               // DT_RANK
#define HID 256             // HIDDEN
#define KCONV 576           // 64*9
#define NCH 16              // chunks
#define TCH 256             // timesteps per chunk

// packed f32x2 FMA (FFMA2) — PTX-only, doubles fp32 FMA throughput
union F2LL { float2 f; unsigned long long u; };
__device__ __forceinline__ float2 ffma2(float2 a, float2 b, float2 c){
    F2LL A, Bv, Cv, D;
    A.f = a; Bv.f = b; Cv.f = c;
    asm("fma.rn.f32x2 %0, %1, %2, %3;" : "=l"(D.u) : "l"(A.u), "l"(Bv.u), "l"(Cv.u));
    return D.f;
}

// ------------------------- scratch buffers (device globals) -------------------------
__device__ float g_c1   [BB*CC*HH*WW];      // conv1 out NCHW
__device__ float g_t    [MM*CC];            // tokens (B,L,64), residual accumulator
__device__ float g_ln   [MM*CC];            // LN output (reused)
__device__ float g_xz   [MM*2*DIN];         // in_proj out: [:,:128]=xin, [:,128:]=z
__device__ float g_xc   [MM*DIN];           // conv1d+silu out (row major)
__device__ float g_xc4  [MM*DIN];           // same, blocked (B, L/4, 128, 4)
__device__ float g_dbl  [MM*132];           // x_proj out (dt|B|C)
__device__ float g_d4   [MM*DIN];           // delta blocked (B, L/4, 128, 4)
__device__ float g_P    [BB*NCH*DIN*DST];   // per-chunk decay
__device__ float g_S    [BB*NCH*DIN*DST];   // per-chunk local final state
__device__ float g_Hi   [BB*NCH*DIN*DST];   // per-chunk initial state
__device__ float g_yg   [MM*DIN];           // gated y
__device__ float g_h1   [MM*HID];           // fc1 out
__device__ float g_g    [MM*HID];           // dwconv+gelu out
__device__ float g_w1t  [KCONV*CC];         // conv1 weight transposed [k][co]
__device__ float g_w2t  [KCONV*CC];         // conv2 weight transposed

// ------------------------- weight transpose prep -------------------------
__global__ void prep_kernel(const float* __restrict__ w1, const float* __restrict__ w2){
    int i = blockIdx.x*256 + threadIdx.x;
    if (i < KCONV*CC){
        int k = i >> 6, co = i & 63;
        g_w1t[i] = w1[co*KCONV + k];
        g_w2t[i] = w2[co*KCONV + k];
    }
}

// ------------------------- implicit-GEMM 3x3 conv, 32-w x 64-co tiles (256 blocks) -------------------------
// MODE 0: out = relu(conv(x)+b) -> g_c1 (NCHW)
// MODE 1: out = conv(g_c1)+b    -> g_t  (token layout B,L,64)
template<int MODE>
__global__ void __launch_bounds__(256) conv3_kernel(const float* __restrict__ in,
                                                    const float* __restrict__ wt,
                                                    const float* __restrict__ bias){
    __shared__ float As[32][17];
    __shared__ __align__(16) float Bs[16*68];
    int blk = blockIdx.x;
    int b = blk >> 7, rest = blk & 127;
    int hh = rest >> 1, wh = rest & 1;            // w-half: rows wh*32..wh*32+31
    int t = threadIdx.x, tx = t & 15, ty = t >> 4;
    float2 acc[2][2] = {};
    int aw = t >> 3, ak2 = (t & 7) << 1;          // A fill: 2 elems/thread
    int bk = t >> 4, bcg = (t & 15) << 2;
    for (int kt = 0; kt < KCONV; kt += 16){
        #pragma unroll
        for (int j = 0; j < 2; j++){
            int k = kt + ak2 + j;
            int ci = k / 9, r = k - ci*9;
            int ky = r / 3, kx = r - ky*3;
            int y = hh + ky - 1, x = (wh<<5) + aw + kx - 1;
            float v = 0.f;
            if (y >= 0 && y < 64 && x >= 0 && x < 64)
                v = in[(((b<<6)+ci)<<12) + (y<<6) + x];
            As[aw][ak2+j] = v;
        }
        float4 wv = *(const float4*)(wt + (kt+bk)*64 + bcg);
        *(float4*)&Bs[bk*68 + bcg] = wv;
        __syncthreads();
        #pragma unroll
        for (int k = 0; k < 16; k++){
            float a0 = As[(ty<<1)+0][k], a1 = As[(ty<<1)+1][k];
            float4 bv = *(const float4*)&Bs[k*68 + (tx<<2)];
            float2 blo = make_float2(bv.x, bv.y), bhi = make_float2(bv.z, bv.w);
            float2 a0p = make_float2(a0, a0), a1p = make_float2(a1, a1);
            acc[0][0] = ffma2(a0p, blo, acc[0][0]);
            acc[0][1] = ffma2(a0p, bhi, acc[0][1]);
            acc[1][0] = ffma2(a1p, blo, acc[1][0]);
            acc[1][1] = ffma2(a1p, bhi, acc[1][1]);
        }
        __syncthreads();
    }
    #pragma unroll
    for (int i = 0; i < 2; i++){
        int w = (wh<<5) + (ty<<1) + i;
        #pragma unroll
        for (int jp = 0; jp < 2; jp++){
            #pragma unroll
            for (int j = 0; j < 2; j++){
                int co = (tx<<2) + jp*2 + j;
                float v = (j ? acc[i][jp].y : acc[i][jp].x) + bias[co];
                if (MODE == 0)
                    g_c1[(((b<<6)+co)<<12) + (hh<<6) + w] = fmaxf(v, 0.f);
                else
                    g_t[(((b<<12) + (hh<<6) + w)<<6) + co] = v;
            }
        }
    }
}

// ------------------------- SGEMM 64x64 tiles: out[M,N] = A[M,K] @ W[N,K]^T -------------------------
#define EPI_STORE 0
#define EPI_STORE_BIAS 1
#define EPI_ADD 2
#define EPI_FINAL 3
template<int EPI>
__global__ void __launch_bounds__(256) gemm_kernel(const float* __restrict__ A,
                                                   const float* __restrict__ W,
                                                   const float* __restrict__ bias,
                                                   float* __restrict__ out,
                                                   int M, int N, int K,
                                                   const float* __restrict__ xres,
                                                   const float* __restrict__ tres){
    __shared__ float As[64][17];
    __shared__ __align__(16) float Bs[16*68];
    int t = threadIdx.x, tx = t & 15, ty = t >> 4;
    int m0 = blockIdx.x << 6, n0 = blockIdx.y << 6;
    float2 acc[4][2] = {};
    int am = t >> 2, akg = (t & 3) << 2;
    int bn = t >> 2, bkg = (t & 3) << 2;
    for (int kt = 0; kt < K; kt += 16){
        float4 av = *(const float4*)(A + (size_t)(m0+am)*K + kt + akg);
        As[am][akg+0] = av.x; As[am][akg+1] = av.y;
        As[am][akg+2] = av.z; As[am][akg+3] = av.w;
        float4 wv = make_float4(0.f,0.f,0.f,0.f);
        if (n0 + bn < N)
            wv = *(const float4*)(W + (size_t)(n0+bn)*K + kt + bkg);
        Bs[(bkg+0)*68 + bn] = wv.x; Bs[(bkg+1)*68 + bn] = wv.y;
        Bs[(bkg+2)*68 + bn] = wv.z; Bs[(bkg+3)*68 + bn] = wv.w;
        __syncthreads();
        #pragma unroll
        for (int k = 0; k < 16; k++){
            float4 bv = *(const float4*)&Bs[k*68 + (tx<<2)];
            float2 blo = make_float2(bv.x, bv.y), bhi = make_float2(bv.z, bv.w);
            #pragma unroll
            for (int i = 0; i < 4; i++){
                float a = As[(ty<<2)+i][k];
                float2 ap = make_float2(a, a);
                acc[i][0] = ffma2(ap, blo, acc[i][0]);
                acc[i][1] = ffma2(ap, bhi, acc[i][1]);
            }
        }
        __syncthreads();
    }
    #pragma unroll
    for (int i = 0; i < 4; i++){
        int m = m0 + (ty<<2) + i;
        #pragma unroll
        for (int jp = 0; jp < 2; jp++){
            #pragma unroll
            for (int j = 0; j < 2; j++){
                int n = n0 + (tx<<2) + jp*2 + j;
                float v = j ? acc[i][jp].y : acc[i][jp].x;
                if (EPI == EPI_STORE){
                    if (n < N) out[(size_t)m*N + n] = v;
                } else if (EPI == EPI_STORE_BIAS){
                    out[(size_t)m*N + n] = v + bias[n];
                } else if (EPI == EPI_ADD){
                    out[(size_t)m*N + n] += v;
                } else {
                    int b = m >> 12, l = m & 4095;
                    size_t oi = ((size_t)(b*64 + n))*4096 + l;
                    out[oi] = xres[oi] + tres[(size_t)m*64 + n] + v + bias[n];
                }
            }
        }
    }
}

// ------------------------- SGEMM 32x64 tiles (N=64 exact) for better occupancy -------------------------
template<int EPI>
__global__ void __launch_bounds__(256) gemm32_kernel(const float* __restrict__ A,
                                                     const float* __restrict__ W,
                                                     const float* __restrict__ bias,
                                                     float* __restrict__ out,
                                                     int K,
                                                     const float* __restrict__ xres,
                                                     const float* __restrict__ tres){
    __shared__ float As[32][17];
    __shared__ __align__(16) float Bs[16*68];
    int t = threadIdx.x, tx = t & 15, ty = t >> 4;
    int m0 = blockIdx.x << 5;
    float2 acc[2][2] = {};
    int am = t >> 3, ak2 = (t & 7) << 1;
    int bn = t >> 2, bkg = (t & 3) << 2;
    for (int kt = 0; kt < K; kt += 16){
        float2 av = *(const float2*)(A + (size_t)(m0+am)*K + kt + ak2);
        As[am][ak2+0] = av.x; As[am][ak2+1] = av.y;
        float4 wv = *(const float4*)(W + (size_t)bn*K + kt + bkg);
        Bs[(bkg+0)*68 + bn] = wv.x; Bs[(bkg+1)*68 + bn] = wv.y;
        Bs[(bkg+2)*68 + bn] = wv.z; Bs[(bkg+3)*68 + bn] = wv.w;
        __syncthreads();
        #pragma unroll
        for (int k = 0; k < 16; k++){
            float4 bv = *(const float4*)&Bs[k*68 + (tx<<2)];
            float2 blo = make_float2(bv.x, bv.y), bhi = make_float2(bv.z, bv.w);
            float a0 = As[(ty<<1)+0][k], a1 = As[(ty<<1)+1][k];
            float2 a0p = make_float2(a0, a0), a1p = make_float2(a1, a1);
            acc[0][0] = ffma2(a0p, blo, acc[0][0]);
            acc[0][1] = ffma2(a0p, bhi, acc[0][1]);
            acc[1][0] = ffma2(a1p, blo, acc[1][0]);
            acc[1][1] = ffma2(a1p, bhi, acc[1][1]);
        }
        __syncthreads();
    }
    #pragma unroll
    for (int i = 0; i < 2; i++){
        int m = m0 + (ty<<1) + i;
        #pragma unroll
        for (int jp = 0; jp < 2; jp++){
            #pragma unroll
            for (int j = 0; j < 2; j++){
                int n = (tx<<2) + jp*2 + j;
                float v = j ? acc[i][jp].y : acc[i][jp].x;
                if (EPI == EPI_ADD){
                    out[(size_t)m*64 + n] += v;
                } else { // FINAL
                    int b = m >> 12, l = m & 4095;
                    size_t oi = ((size_t)(b*64 + n))*4096 + l;
                    out[oi] = xres[oi] + tres[(size_t)m*64 + n] + v + bias[n];
                }
            }
        }
    }
}

// ------------------------- layernorm over 64 feats -------------------------
__global__ void ln_kernel(const float* __restrict__ in, const float* __restrict__ w,
                          const float* __restrict__ b, float* __restrict__ out){
    int m = blockIdx.x*8 + (threadIdx.x >> 5);
    int lane = threadIdx.x & 31;
    float x0 = in[m*64 + lane], x1 = in[m*64 + 32 + lane];
    float s = x0 + x1;
    #pragma unroll
    for (int o = 16; o > 0; o >>= 1) s += __shfl_xor_sync(0xffffffffu, s, o);
    float mean = s * (1.f/64.f);
    float d0 = x0 - mean, d1 = x1 - mean;
    float v = d0*d0 + d1*d1;
    #pragma unroll
    for (int o = 16; o > 0; o >>= 1) v += __shfl_xor_sync(0xffffffffu, v, o);
    float inv = rsqrtf(v * (1.f/64.f) + 1e-5f);
    out[m*64 + lane]      = d0*inv*w[lane]    + b[lane];
    out[m*64 + 32 + lane] = d1*inv*w[lane+32] + b[lane+32];
}

// ------------------------- causal dwconv1d + silu -------------------------
__global__ void conv1d_kernel(const float* __restrict__ cw, const float* __restrict__ cb){
    int idx = blockIdx.x*256 + threadIdx.x;           // M*128
    int d = idx & 127, m = idx >> 7;
    int b = m >> 12, tt = m & 4095;
    float acc = cb[d];
    #pragma unroll
    for (int k = 0; k < 4; k++){
        int t2 = tt - 3 + k;
        if (t2 >= 0) acc = fmaf(cw[d*4 + k], g_xz[(size_t)((b<<12)+t2)*256 + d], acc);
    }
    float s = acc / (1.f + expf(-acc));
    g_xc[(size_t)m*128 + d] = s;
    int q = tt >> 2, r = tt & 3;
    g_xc4[(((size_t)(b*1024+q)*128 + d)<<2) + r] = s;
}

// ------------------------- delta = softplus(dt @ dtw^T + dtb), blocked layout -------------------------
__global__ void dtrepack_kernel(const float* __restrict__ dtw, const float* __restrict__ dtb){
    int m = blockIdx.x, d = threadIdx.x;              // 8192 x 128
    int b = m >> 12, tt = m & 4095, q = tt >> 2, r = tt & 3;
    const float* row = g_dbl + (size_t)m*132;
    float x = dtb[d];
    x = fmaf(row[0], dtw[d*4+0], x);
    x = fmaf(row[1], dtw[d*4+1], x);
    x = fmaf(row[2], dtw[d*4+2], x);
    x = fmaf(row[3], dtw[d*4+3], x);
    float sp = fmaxf(x, 0.f) + log1pf(expf(-fabsf(x)));
    g_d4[(((size_t)(b*1024+q)*128 + d)<<2) + r] = sp;
}

// ------------------------- scan pass 1a: per-chunk summaries (S, P) -------------------------
__global__ void __launch_bounds__(256) scan1_kernel(const float* __restrict__ Alog){
    __shared__ float Bsh[64][64];
    int dg = blockIdx.x, c = blockIdx.y, b = blockIdx.z;
    int tid = threadIdx.x, w = tid >> 5, lane = tid & 31;
    int d = dg*8 + w, n0 = lane, n1 = lane + 32;
    float A0 = -__expf(Alog[d*64 + n0]);
    float A1 = -__expf(Alog[d*64 + n1]);
    float h0 = 0.f, h1 = 0.f, sd = 0.f;
    const float4* dp4 = (const float4*)g_d4  + (size_t)b*1024*128 + d;
    const float4* up4 = (const float4*)g_xc4 + (size_t)b*1024*128 + d;
    for (int s = 0; s < 4; s++){
        int m0 = b*4096 + c*256 + s*64;
        __syncthreads();
        #pragma unroll
        for (int rep = 0; rep < 4; rep++){
            int i = rep*256 + tid; int row = i >> 4, v = i & 15;
            *(float4*)&Bsh[row][v*4] = *(const float4*)(g_dbl + (size_t)(m0+row)*132 + 4 + v*4);
        }
        __syncthreads();
        int qb = (c*256 + s*64) >> 2;
        float4 dq = dp4[(size_t)qb*128], uq = up4[(size_t)qb*128];
        for (int qi = 0; qi < 16; qi++){
            float4 dc = dq, uc = uq;
            if (qi < 15){ dq = dp4[(size_t)(qb+qi+1)*128]; uq = up4[(size_t)(qb+qi+1)*128]; }
            float dv[4], uv[4];
            *(float4*)dv = dc; *(float4*)uv = uc;
            #pragma unroll
            for (int j = 0; j < 4; j++){
                int row = qi*4 + j;
                float du = dv[j]*uv[j];
                h0 = fmaf(h0, __expf(dv[j]*A0), du*Bsh[row][n0]);
                h1 = fmaf(h1, __expf(dv[j]*A1), du*Bsh[row][n1]);
                sd += dv[j];
            }
        }
    }
    size_t base = ((size_t)((b*NCH + c)*128 + d))*64;
    g_S[base + n0] = h0;              g_S[base + n1] = h1;
    g_P[base + n0] = __expf(sd*A0);   g_P[base + n1] = __expf(sd*A1);
}

// ------------------------- scan pass 1b: combine chunk summaries -> h_init -------------------------
__global__ void scan2_kernel(){
    int wg = blockIdx.x*4 + (threadIdx.x >> 5);  // 0..255 = (b,d)
    int lane = threadIdx.x & 31;
    int b = wg >> 7, d = wg & 127;
    float h0 = 0.f, h1 = 0.f;
    for (int c = 0; c < NCH; c++){
        size_t base = ((size_t)((b*NCH + c)*128 + d))*64;
        g_Hi[base + lane]      = h0;
        g_Hi[base + 32 + lane] = h1;
        h0 = fmaf(g_P[base + lane],      h0, g_S[base + lane]);
        h1 = fmaf(g_P[base + 32 + lane], h1, g_S[base + 32 + lane]);
    }
}

// ------------------------- scan pass 2: full scan per chunk + D-term + silu(z) gate -------------------------
__global__ void __launch_bounds__(256) scan3_kernel(const float* __restrict__ Alog,
                                                    const float* __restrict__ Dp){
    __shared__ float Bsh[64][64];
    __shared__ float Csh[64][64];
    __shared__ float Zsh[64][8];
    int dg = blockIdx.x, c = blockIdx.y, b = blockIdx.z;
    int tid = threadIdx.x, w = tid >> 5, lane = tid & 31;
    int d = dg*8 + w, n0 = lane, n1 = lane + 32;
    float A0 = -__expf(Alog[d*64 + n0]);
    float A1 = -__expf(Alog[d*64 + n1]);
    float Dd = Dp[d];
    size_t hbase = ((size_t)((b*NCH + c)*128 + d))*64;
    float h0 = g_Hi[hbase + n0], h1 = g_Hi[hbase + n1];
    const float4* dp4 = (const float4*)g_d4  + (size_t)b*1024*128 + d;
    const float4* up4 = (const float4*)g_xc4 + (size_t)b*1024*128 + d;
    for (int s = 0; s < 4; s++){
        int m0 = b*4096 + c*256 + s*64;
        __syncthreads();
        #pragma unroll
        for (int rep = 0; rep < 4; rep++){
            int i = rep*256 + tid; int row = i >> 4, v = i & 15;
            const float* rb = g_dbl + (size_t)(m0+row)*132;
            *(float4*)&Bsh[row][v*4] = *(const float4*)(rb + 4  + v*4);
            *(float4*)&Csh[row][v*4] = *(const float4*)(rb + 68 + v*4);
        }
        if (tid < 128){
            int row = tid >> 1, hf = tid & 1;
            *(float4*)&Zsh[row][hf*4] =
                *(const float4*)(g_xz + (size_t)(m0+row)*256 + 128 + dg*8 + hf*4);
        }
        __syncthreads();
        int qb = (c*256 + s*64) >> 2;
        float4 dq = dp4[(size_t)qb*128], uq = up4[(size_t)qb*128];
        for (int qi = 0; qi < 16; qi++){
            float4 dc = dq, uc = uq;
            if (qi < 15){ dq = dp4[(size_t)(qb+qi+1)*128]; uq = up4[(size_t)(qb+qi+1)*128]; }
            float dv[4], uv[4];
            *(float4*)dv = dc; *(float4*)uv = uc;
            #pragma unroll
            for (int j = 0; j < 4; j++){
                int row = qi*4 + j;
                float du = dv[j]*uv[j];
                h0 = fmaf(h0, __expf(dv[j]*A0), du*Bsh[row][n0]);
                h1 = fmaf(h1, __expf(dv[j]*A1), du*Bsh[row][n1]);
                float p = fmaf(h0, Csh[row][n0], h1*Csh[row][n1]);
                #pragma unroll
                for (int o = 16; o > 0; o >>= 1) p += __shfl_xor_sync(0xffffffffu, p, o);
                if (lane == 0){
                    float z = Zsh[row][w];
                    float sz = z / (1.f + __expf(-z));
                    g_yg[(size_t)(m0+row)*128 + d] = (p + uv[j]*Dd) * sz;
                }
            }
        }
    }
}

// ------------------------- depthwise 3x3 conv + exact gelu -------------------------
__global__ void dwconv_kernel(const float* __restrict__ dww, const float* __restrict__ dwb){
    int blk = blockIdx.x;                              // 8192 = (b,l)
    int b = blk >> 12, l = blk & 4095;
    int y = l >> 6, x = l & 63;
    int ch = threadIdx.x;                              // 256
    float acc = dwb[ch];
    #pragma unroll
    for (int ky = 0; ky < 3; ky++){
        int yy = y + ky - 1;
        if (yy < 0 || yy > 63) continue;
        #pragma unroll
        for (int kx = 0; kx < 3; kx++){
            int xx = x + kx - 1;
            if (xx < 0 || xx > 63) continue;
            acc = fmaf(dww[ch*9 + ky*3 + kx],
                       g_h1[(size_t)((b<<12) + (yy<<6) + xx)*256 + ch], acc);
        }
    }
    g_g[(size_t)blk*256 + ch] = 0.5f*acc*(1.f + erff(acc*0.70710678118654752f));
}

// ------------------------- host launch -------------------------
extern "C" void kernel_launch(void* const* d_in, const int* in_sizes, int n_in,
                              void* d_out, int out_size){
    const float* x        = (const float*)d_in[0];
    const float* conv1_w  = (const float*)d_in[1];
    const float* conv1_b  = (const float*)d_in[2];
    const float* conv2_w  = (const float*)d_in[3];
    const float* conv2_b  = (const float*)d_in[4];
    const float* ln1_w    = (const float*)d_in[5];
    const float* ln1_b    = (const float*)d_in[6];
    const float* ln2_w    = (const float*)d_in[7];
    const float* ln2_b    = (const float*)d_in[8];
    const float* in_proj  = (const float*)d_in[9];
    const float* c1d_w    = (const float*)d_in[10];
    const float* c1d_b    = (const float*)d_in[11];
    const float* xproj_w  = (const float*)d_in[12];
    const float* dtp_w    = (const float*)d_in[13];
    const float* dtp_b    = (const float*)d_in[14];
    const float* A_log    = (const float*)d_in[15];
    const float* D_param  = (const float*)d_in[16];
    const float* outp_w   = (const float*)d_in[17];
    const float* fc1_w    = (const float*)d_in[18];
    const float* fc1_b    = (const float*)d_in[19];
    const float* dw_w     = (const float*)d_in[20];
    const float* dw_b     = (const float*)d_in[21];
    const float* fc2_w    = (const float*)d_in[22];
    const float* fc2_b    = (const float*)d_in[23];
    float* out = (float*)d_out;

    float *p_t, *p_ln, *p_xz, *p_xc, *p_dbl, *p_yg, *p_h1, *p_g, *p_c1;
    cudaGetSymbolAddress((void**)&p_t,   g_t);
    cudaGetSymbolAddress((void**)&p_ln,  g_ln);
    cudaGetSymbolAddress((void**)&p_xz,  g_xz);
    cudaGetSymbolAddress((void**)&p_xc,  g_xc);
    cudaGetSymbolAddress((void**)&p_dbl, g_dbl);
    cudaGetSymbolAddress((void**)&p_yg,  g_yg);
    cudaGetSymbolAddress((void**)&p_h1,  g_h1);
    cudaGetSymbolAddress((void**)&p_g,   g_g);
    cudaGetSymbolAddress((void**)&p_c1,  g_c1);

    prep_kernel<<<(KCONV*CC + 255)/256, 256>>>(conv1_w, conv2_w);

    float *p_w1t, *p_w2t;
    cudaGetSymbolAddress((void**)&p_w1t, g_w1t);
    cudaGetSymbolAddress((void**)&p_w2t, g_w2t);

    conv3_kernel<0><<<BB*HH*2, 256>>>(x,    p_w1t, conv1_b);
    conv3_kernel<1><<<BB*HH*2, 256>>>(p_c1, p_w2t, conv2_b);

    // mamba branch
    ln_kernel<<<MM/8, 256>>>(p_t, ln1_w, ln1_b, p_ln);
    gemm_kernel<EPI_STORE><<<dim3(MM/64, 4), 256>>>(p_ln, in_proj, nullptr, p_xz,
                                                    MM, 256, 64, nullptr, nullptr);
    conv1d_kernel<<<MM*DIN/256, 256>>>(c1d_w, c1d_b);
    gemm_kernel<EPI_STORE><<<dim3(MM/64, 3), 256>>>(p_xc, xproj_w, nullptr, p_dbl,
                                                    MM, 132, 128, nullptr, nullptr);
    dtrepack_kernel<<<MM, 128>>>(dtp_w, dtp_b);

    scan1_kernel<<<dim3(16, NCH, BB), 256>>>(A_log);
    scan2_kernel<<<64, 128>>>();
    scan3_kernel<<<dim3(16, NCH, BB), 256>>>(A_log, D_param);

    gemm32_kernel<EPI_ADD><<<MM/32, 256>>>(p_yg, outp_w, nullptr, p_t,
                                           128, nullptr, nullptr);

    // FFN branch
    ln_kernel<<<MM/8, 256>>>(p_t, ln2_w, ln2_b, p_ln);
    gemm_kernel<EPI_STORE_BIAS><<<dim3(MM/64, 4), 256>>>(p_ln, fc1_w, fc1_b, p_h1,
                                                         MM, 256, 64, nullptr, nullptr);
    dwconv_kernel<<<MM, 256>>>(dw_w, dw_b);
    gemm32_kernel<EPI_FINAL><<<MM/32, 256>>>(p_g, fc2_w, fc2_b, out,
                                             256, x, p_t);
}

// round 5
// speedup vs baseline: 1.0940x; 1.0940x over previous
#include <cuda_runtime.h>
#include <math.h>

#define BB 2
#define CC 64
#define HH 64
#define WW 64
#define LL 4096
#define MM (BB*LL)          // 8192 tokens
#define DIN 128             // D_INNER
#define DST 64              // D_STATE
#define DTR 4               // DT_RANK
#define HID 256             // HIDDEN
#define KCONV 576           // 64*9
#define NCH 16              // chunks

// ------------------------- scratch buffers (device globals) -------------------------
__device__ float g_c1   [BB*CC*HH*WW];      // conv1 out NCHW
__device__ float g_t    [MM*CC];            // tokens (B,L,64), residual accumulator
__device__ float g_xz   [MM*2*DIN];         // in_proj out: [:,:128]=xin, [:,128:]=z
__device__ float g_xc   [MM*DIN];           // conv1d+silu out (row major)
__device__ float g_xc4  [MM*DIN];           // same, blocked (B, L/4, 128, 4)
__device__ float g_dbl  [MM*132];           // x_proj out (dt|B|C)
__device__ float g_d4   [MM*DIN];           // delta blocked (B, L/4, 128, 4)
__device__ float g_P    [BB*NCH*DIN*DST];   // per-chunk decay
__device__ float g_S    [BB*NCH*DIN*DST];   // per-chunk local final state
__device__ float g_Hi   [BB*NCH*DIN*DST];   // per-chunk initial state
__device__ float g_yg   [MM*DIN];           // gated y
__device__ float g_h1   [MM*HID];           // fc1 out
__device__ float g_g    [MM*HID];           // dwconv+gelu out
__device__ float g_w1t  [KCONV*CC];         // conv1 weight reordered [(seg,ci)][co]
__device__ float g_w2t  [KCONV*CC];         // conv2 weight reordered

// ------------------------- weight reorder prep: [(ky*3+kx)*64+ci][co] -------------------------
__global__ void prep_kernel(const float* __restrict__ w1, const float* __restrict__ w2){
    int i = blockIdx.x*256 + threadIdx.x;
    if (i < KCONV*CC){
        int k = i >> 6, co = i & 63;
        int seg = k >> 6, ci = k & 63;                // k = seg*64 + ci
        int src = co*KCONV + ci*9 + seg;              // w[co][ci][ky][kx]
        g_w1t[i] = w1[src];
        g_w2t[i] = w2[src];
    }
}

// ------------------------- implicit-GEMM 3x3 conv, K reordered (seg, ci) -------------------------
// MODE 0: out = relu(conv(x)+b) -> g_c1 (NCHW)
// MODE 1: out = conv(g_c1)+b    -> g_t  (token layout B,L,64)
template<int MODE>
__global__ void __launch_bounds__(256) conv3_kernel(const float* __restrict__ in,
                                                    const float* __restrict__ wt,
                                                    const float* __restrict__ bias){
    __shared__ float As[64][17];
    __shared__ __align__(16) float Bs[16*68];
    int blk = blockIdx.x;
    int b = blk >> 6, hh = blk & 63;
    int t = threadIdx.x, tx = t & 15, ty = t >> 4;
    float acc[4][4] = {};
    int aw = t & 63, ci0 = t >> 6;                    // A fill: w=aw, ci = ci0+4j
    int bk = t >> 4, bcg = (t & 15) << 2;             // B fill
    #pragma unroll 1
    for (int seg = 0; seg < 9; seg++){
        int ky = seg / 3, kx = seg - ky*3;
        int y = hh + ky - 1;
        int x = aw + kx - 1;
        bool ok = (y >= 0) && (y < 64) && (x >= 0) && (x < 64);
        const float* src = in + (((size_t)b << 18) + (y << 6) + x);   // + ci*4096
        #pragma unroll 1
        for (int kc = 0; kc < 4; kc++){               // 16-ci chunks
            #pragma unroll
            for (int jj = 0; jj < 4; jj++){
                int cis = kc*16 + ci0 + jj*4;
                As[aw][ci0 + jj*4] = ok ? src[(size_t)cis << 12] : 0.f;
            }
            float4 wv = *(const float4*)(wt + (size_t)(seg*64 + kc*16 + bk)*64 + bcg);
            *(float4*)&Bs[bk*68 + bcg] = wv;
            __syncthreads();
            #pragma unroll
            for (int k = 0; k < 16; k++){
                float a0 = As[(ty<<2)+0][k], a1 = As[(ty<<2)+1][k];
                float a2 = As[(ty<<2)+2][k], a3 = As[(ty<<2)+3][k];
                float4 bv = *(const float4*)&Bs[k*68 + (tx<<2)];
                acc[0][0] = fmaf(a0,bv.x,acc[0][0]); acc[0][1] = fmaf(a0,bv.y,acc[0][1]);
                acc[0][2] = fmaf(a0,bv.z,acc[0][2]); acc[0][3] = fmaf(a0,bv.w,acc[0][3]);
                acc[1][0] = fmaf(a1,bv.x,acc[1][0]); acc[1][1] = fmaf(a1,bv.y,acc[1][1]);
                acc[1][2] = fmaf(a1,bv.z,acc[1][2]); acc[1][3] = fmaf(a1,bv.w,acc[1][3]);
                acc[2][0] = fmaf(a2,bv.x,acc[2][0]); acc[2][1] = fmaf(a2,bv.y,acc[2][1]);
                acc[2][2] = fmaf(a2,bv.z,acc[2][2]); acc[2][3] = fmaf(a2,bv.w,acc[2][3]);
                acc[3][0] = fmaf(a3,bv.x,acc[3][0]); acc[3][1] = fmaf(a3,bv.y,acc[3][1]);
                acc[3][2] = fmaf(a3,bv.z,acc[3][2]); acc[3][3] = fmaf(a3,bv.w,acc[3][3]);
            }
            __syncthreads();
        }
    }
    #pragma unroll
    for (int i = 0; i < 4; i++){
        int w = (ty<<2)+i;
        #pragma unroll
        for (int j = 0; j < 4; j++){
            int co = (tx<<2)+j;
            float v = acc[i][j] + bias[co];
            if (MODE == 0)
                g_c1[(((b<<6)+co)<<12) + (hh<<6) + w] = fmaxf(v, 0.f);
            else
                g_t[(((b<<12) + (hh<<6) + w)<<6) + co] = v;
        }
    }
}

// ------------------------- SGEMM with fused LayerNorm on A (K=64 only) -------------------------
// out[M,N] = LN(A)[M,64] @ W[N,64]^T (+bias)
template<int HASB>
__global__ void __launch_bounds__(256) gemmln_kernel(const float* __restrict__ A,
                                                     const float* __restrict__ W,
                                                     const float* __restrict__ lnw,
                                                     const float* __restrict__ lnb,
                                                     const float* __restrict__ bias,
                                                     float* __restrict__ out, int N){
    __shared__ float As[64][68];
    __shared__ __align__(16) float Bs[16*68];
    int t = threadIdx.x, tx = t & 15, ty = t >> 4;
    int m0 = blockIdx.x << 6, n0 = blockIdx.y << 6;
    // ---- load A tile + LN ----
    {
        int row = t >> 2, q = t & 3;                  // 4 threads per row, 16 cols each
        float v[16];
        const float* ap = A + (size_t)(m0+row)*64 + q*16;
        #pragma unroll
        for (int j = 0; j < 16; j += 4){
            float4 f = *(const float4*)(ap + j);
            v[j] = f.x; v[j+1] = f.y; v[j+2] = f.z; v[j+3] = f.w;
        }
        float s = 0.f;
        #pragma unroll
        for (int j = 0; j < 16; j++) s += v[j];
        s += __shfl_xor_sync(0xffffffffu, s, 1);
        s += __shfl_xor_sync(0xffffffffu, s, 2);
        float mean = s * (1.f/64.f);
        float var = 0.f;
        #pragma unroll
        for (int j = 0; j < 16; j++){ float d = v[j]-mean; var += d*d; }
        var += __shfl_xor_sync(0xffffffffu, var, 1);
        var += __shfl_xor_sync(0xffffffffu, var, 2);
        float inv = rsqrtf(var * (1.f/64.f) + 1e-5f);
        #pragma unroll
        for (int j = 0; j < 16; j++){
            int col = q*16 + j;
            As[row][col] = (v[j]-mean)*inv*lnw[col] + lnb[col];
        }
    }
    float acc[4][4] = {};
    int bn = t >> 2, bkg = (t & 3) << 2;
    for (int kt = 0; kt < 64; kt += 16){
        float4 wv = *(const float4*)(W + (size_t)(n0+bn)*64 + kt + bkg);
        Bs[(bkg+0)*68 + bn] = wv.x; Bs[(bkg+1)*68 + bn] = wv.y;
        Bs[(bkg+2)*68 + bn] = wv.z; Bs[(bkg+3)*68 + bn] = wv.w;
        __syncthreads();
        #pragma unroll
        for (int k = 0; k < 16; k++){
            float a0 = As[(ty<<2)+0][kt+k], a1 = As[(ty<<2)+1][kt+k];
            float a2 = As[(ty<<2)+2][kt+k], a3 = As[(ty<<2)+3][kt+k];
            float4 bv = *(const float4*)&Bs[k*68 + (tx<<2)];
            acc[0][0] = fmaf(a0,bv.x,acc[0][0]); acc[0][1] = fmaf(a0,bv.y,acc[0][1]);
            acc[0][2] = fmaf(a0,bv.z,acc[0][2]); acc[0][3] = fmaf(a0,bv.w,acc[0][3]);
            acc[1][0] = fmaf(a1,bv.x,acc[1][0]); acc[1][1] = fmaf(a1,bv.y,acc[1][1]);
            acc[1][2] = fmaf(a1,bv.z,acc[1][2]); acc[1][3] = fmaf(a1,bv.w,acc[1][3]);
            acc[2][0] = fmaf(a2,bv.x,acc[2][0]); acc[2][1] = fmaf(a2,bv.y,acc[2][1]);
            acc[2][2] = fmaf(a2,bv.z,acc[2][2]); acc[2][3] = fmaf(a2,bv.w,acc[2][3]);
            acc[3][0] = fmaf(a3,bv.x,acc[3][0]); acc[3][1] = fmaf(a3,bv.y,acc[3][1]);
            acc[3][2] = fmaf(a3,bv.z,acc[3][2]); acc[3][3] = fmaf(a3,bv.w,acc[3][3]);
        }
        __syncthreads();
    }
    #pragma unroll
    for (int i = 0; i < 4; i++){
        int m = m0 + (ty<<2) + i;
        #pragma unroll
        for (int j = 0; j < 4; j++){
            int n = n0 + (tx<<2) + j;
            float v = acc[i][j];
            if (HASB) v += bias[n];
            out[(size_t)m*N + n] = v;
        }
    }
}

// ------------------------- generic SGEMM: out[M,N] = A[M,K] @ W[N,K]^T -------------------------
#define EPI_STORE 0
#define EPI_ADD 2
#define EPI_FINAL 3
template<int EPI>
__global__ void __launch_bounds__(256) gemm_kernel(const float* __restrict__ A,
                                                   const float* __restrict__ W,
                                                   const float* __restrict__ bias,
                                                   float* __restrict__ out,
                                                   int M, int N, int K,
                                                   const float* __restrict__ xres,
                                                   const float* __restrict__ tres){
    __shared__ float As[64][17];
    __shared__ __align__(16) float Bs[16*68];
    int t = threadIdx.x, tx = t & 15, ty = t >> 4;
    int m0 = blockIdx.x << 6, n0 = blockIdx.y << 6;
    float acc[4][4] = {};
    int am = t >> 2, akg = (t & 3) << 2;
    int bn = t >> 2, bkg = (t & 3) << 2;
    for (int kt = 0; kt < K; kt += 16){
        float4 av = *(const float4*)(A + (size_t)(m0+am)*K + kt + akg);
        As[am][akg+0] = av.x; As[am][akg+1] = av.y;
        As[am][akg+2] = av.z; As[am][akg+3] = av.w;
        float4 wv = make_float4(0.f,0.f,0.f,0.f);
        if (n0 + bn < N)
            wv = *(const float4*)(W + (size_t)(n0+bn)*K + kt + bkg);
        Bs[(bkg+0)*68 + bn] = wv.x; Bs[(bkg+1)*68 + bn] = wv.y;
        Bs[(bkg+2)*68 + bn] = wv.z; Bs[(bkg+3)*68 + bn] = wv.w;
        __syncthreads();
        #pragma unroll
        for (int k = 0; k < 16; k++){
            float a0 = As[(ty<<2)+0][k], a1 = As[(ty<<2)+1][k];
            float a2 = As[(ty<<2)+2][k], a3 = As[(ty<<2)+3][k];
            float4 bv = *(const float4*)&Bs[k*68 + (tx<<2)];
            acc[0][0] = fmaf(a0,bv.x,acc[0][0]); acc[0][1] = fmaf(a0,bv.y,acc[0][1]);
            acc[0][2] = fmaf(a0,bv.z,acc[0][2]); acc[0][3] = fmaf(a0,bv.w,acc[0][3]);
            acc[1][0] = fmaf(a1,bv.x,acc[1][0]); acc[1][1] = fmaf(a1,bv.y,acc[1][1]);
            acc[1][2] = fmaf(a1,bv.z,acc[1][2]); acc[1][3] = fmaf(a1,bv.w,acc[1][3]);
            acc[2][0] = fmaf(a2,bv.x,acc[2][0]); acc[2][1] = fmaf(a2,bv.y,acc[2][1]);
            acc[2][2] = fmaf(a2,bv.z,acc[2][2]); acc[2][3] = fmaf(a2,bv.w,acc[2][3]);
            acc[3][0] = fmaf(a3,bv.x,acc[3][0]); acc[3][1] = fmaf(a3,bv.y,acc[3][1]);
            acc[3][2] = fmaf(a3,bv.z,acc[3][2]); acc[3][3] = fmaf(a3,bv.w,acc[3][3]);
        }
        __syncthreads();
    }
    #pragma unroll
    for (int i = 0; i < 4; i++){
        int m = m0 + (ty<<2) + i;
        #pragma unroll
        for (int j = 0; j < 4; j++){
            int n = n0 + (tx<<2) + j;
            float v = acc[i][j];
            if (EPI == EPI_STORE){
                if (n < N) out[(size_t)m*N + n] = v;
            } else if (EPI == EPI_ADD){
                out[(size_t)m*N + n] += v;
            } else { // FINAL: out NCHW = x + t + gemm + bias
                int b = m >> 12, l = m & 4095;
                size_t oi = ((size_t)(b*64 + n))*4096 + l;
                out[oi] = xres[oi] + tres[(size_t)m*64 + n] + v + bias[n];
            }
        }
    }
}

// ------------------------- causal dwconv1d + silu -------------------------
__global__ void conv1d_kernel(const float* __restrict__ cw, const float* __restrict__ cb){
    int idx = blockIdx.x*256 + threadIdx.x;           // M*128
    int d = idx & 127, m = idx >> 7;
    int b = m >> 12, tt = m & 4095;
    float acc = cb[d];
    #pragma unroll
    for (int k = 0; k < 4; k++){
        int t2 = tt - 3 + k;
        if (t2 >= 0) acc = fmaf(cw[d*4 + k], g_xz[(size_t)((b<<12)+t2)*256 + d], acc);
    }
    float s = acc / (1.f + expf(-acc));
    g_xc[(size_t)m*128 + d] = s;
    int q = tt >> 2, r = tt & 3;
    g_xc4[(((size_t)(b*1024+q)*128 + d)<<2) + r] = s;
}

// ------------------------- delta = softplus(dt @ dtw^T + dtb), blocked layout -------------------------
__global__ void dtrepack_kernel(const float* __restrict__ dtw, const float* __restrict__ dtb){
    int m = blockIdx.x, d = threadIdx.x;              // 8192 x 128
    int b = m >> 12, tt = m & 4095, q = tt >> 2, r = tt & 3;
    const float* row = g_dbl + (size_t)m*132;
    float x = dtb[d];
    x = fmaf(row[0], dtw[d*4+0], x);
    x = fmaf(row[1], dtw[d*4+1], x);
    x = fmaf(row[2], dtw[d*4+2], x);
    x = fmaf(row[3], dtw[d*4+3], x);
    float sp = fmaxf(x, 0.f) + log1pf(expf(-fabsf(x)));
    g_d4[(((size_t)(b*1024+q)*128 + d)<<2) + r] = sp;
}

// ------------------------- scan pass 1a: per-chunk summaries (S, P) -------------------------
__global__ void __launch_bounds__(256) scan1_kernel(const float* __restrict__ Alog){
    __shared__ float Bsh[64][64];
    int dg = blockIdx.x, c = blockIdx.y, b = blockIdx.z;
    int tid = threadIdx.x, w = tid >> 5, lane = tid & 31;
    int d = dg*8 + w, n0 = lane, n1 = lane + 32;
    float A0 = -__expf(Alog[d*64 + n0]);
    float A1 = -__expf(Alog[d*64 + n1]);
    float h0 = 0.f, h1 = 0.f, sd = 0.f;
    const float4* dp4 = (const float4*)g_d4  + (size_t)b*1024*128 + d;
    const float4* up4 = (const float4*)g_xc4 + (size_t)b*1024*128 + d;
    for (int s = 0; s < 4; s++){
        int m0 = b*4096 + c*256 + s*64;
        __syncthreads();
        #pragma unroll
        for (int rep = 0; rep < 4; rep++){
            int i = rep*256 + tid; int row = i >> 4, v = i & 15;
            *(float4*)&Bsh[row][v*4] = *(const float4*)(g_dbl + (size_t)(m0+row)*132 + 4 + v*4);
        }
        __syncthreads();
        int qb = (c*256 + s*64) >> 2;
        float4 dq = dp4[(size_t)qb*128], uq = up4[(size_t)qb*128];
        for (int qi = 0; qi < 16; qi++){
            float4 dc = dq, uc = uq;
            if (qi < 15){ dq = dp4[(size_t)(qb+qi+1)*128]; uq = up4[(size_t)(qb+qi+1)*128]; }
            float dv[4], uv[4];
            *(float4*)dv = dc; *(float4*)uv = uc;
            #pragma unroll
            for (int j = 0; j < 4; j++){
                int row = qi*4 + j;
                float du = dv[j]*uv[j];
                h0 = fmaf(h0, __expf(dv[j]*A0), du*Bsh[row][n0]);
                h1 = fmaf(h1, __expf(dv[j]*A1), du*Bsh[row][n1]);
                sd += dv[j];
            }
        }
    }
    size_t base = ((size_t)((b*NCH + c)*128 + d))*64;
    g_S[base + n0] = h0;              g_S[base + n1] = h1;
    g_P[base + n0] = __expf(sd*A0);   g_P[base + n1] = __expf(sd*A1);
}

// ------------------------- scan pass 1b: combine chunk summaries -> h_init -------------------------
__global__ void scan2_kernel(){
    int wg = blockIdx.x*4 + (threadIdx.x >> 5);  // 0..255 = (b,d)
    int lane = threadIdx.x & 31;
    int b = wg >> 7, d = wg & 127;
    float h0 = 0.f, h1 = 0.f;
    for (int c = 0; c < NCH; c++){
        size_t base = ((size_t)((b*NCH + c)*128 + d))*64;
        g_Hi[base + lane]      = h0;
        g_Hi[base + 32 + lane] = h1;
        h0 = fmaf(g_P[base + lane],      h0, g_S[base + lane]);
        h1 = fmaf(g_P[base + 32 + lane], h1, g_S[base + 32 + lane]);
    }
}

// ------------------------- scan pass 2: full scan per chunk + D-term + silu(z) gate -------------------------
__global__ void __launch_bounds__(256) scan3_kernel(const float* __restrict__ Alog,
                                                    const float* __restrict__ Dp){
    __shared__ float Bsh[64][64];
    __shared__ float Csh[64][64];
    __shared__ float Zsh[64][8];
    int dg = blockIdx.x, c = blockIdx.y, b = blockIdx.z;
    int tid = threadIdx.x, w = tid >> 5, lane = tid & 31;
    int d = dg*8 + w, n0 = lane, n1 = lane + 32;
    float A0 = -__expf(Alog[d*64 + n0]);
    float A1 = -__expf(Alog[d*64 + n1]);
    float Dd = Dp[d];
    size_t hbase = ((size_t)((b*NCH + c)*128 + d))*64;
    float h0 = g_Hi[hbase + n0], h1 = g_Hi[hbase + n1];
    const float4* dp4 = (const float4*)g_d4  + (size_t)b*1024*128 + d;
    const float4* up4 = (const float4*)g_xc4 + (size_t)b*1024*128 + d;
    for (int s = 0; s < 4; s++){
        int m0 = b*4096 + c*256 + s*64;
        __syncthreads();
        #pragma unroll
        for (int rep = 0; rep < 4; rep++){
            int i = rep*256 + tid; int row = i >> 4, v = i & 15;
            const float* rb = g_dbl + (size_t)(m0+row)*132;
            *(float4*)&Bsh[row][v*4] = *(const float4*)(rb + 4  + v*4);
            *(float4*)&Csh[row][v*4] = *(const float4*)(rb + 68 + v*4);
        }
        if (tid < 128){
            int row = tid >> 1, hf = tid & 1;
            *(float4*)&Zsh[row][hf*4] =
                *(const float4*)(g_xz + (size_t)(m0+row)*256 + 128 + dg*8 + hf*4);
        }
        __syncthreads();
        int qb = (c*256 + s*64) >> 2;
        float4 dq = dp4[(size_t)qb*128], uq = up4[(size_t)qb*128];
        for (int qi = 0; qi < 16; qi++){
            float4 dc = dq, uc = uq;
            if (qi < 15){ dq = dp4[(size_t)(qb+qi+1)*128]; uq = up4[(size_t)(qb+qi+1)*128]; }
            float dv[4], uv[4];
            *(float4*)dv = dc; *(float4*)uv = uc;
            #pragma unroll
            for (int j = 0; j < 4; j++){
                int row = qi*4 + j;
                float du = dv[j]*uv[j];
                h0 = fmaf(h0, __expf(dv[j]*A0), du*Bsh[row][n0]);
                h1 = fmaf(h1, __expf(dv[j]*A1), du*Bsh[row][n1]);
                float p = fmaf(h0, Csh[row][n0], h1*Csh[row][n1]);
                #pragma unroll
                for (int o = 16; o > 0; o >>= 1) p += __shfl_xor_sync(0xffffffffu, p, o);
                if (lane == 0){
                    float z = Zsh[row][w];
                    float sz = z / (1.f + __expf(-z));
                    g_yg[(size_t)(m0+row)*128 + d] = (p + uv[j]*Dd) * sz;
                }
            }
        }
    }
}

// ------------------------- depthwise 3x3 conv + exact gelu -------------------------
__global__ void dwconv_kernel(const float* __restrict__ dww, const float* __restrict__ dwb){
    int blk = blockIdx.x;                              // 8192 = (b,l)
    int b = blk >> 12, l = blk & 4095;
    int y = l >> 6, x = l & 63;
    int ch = threadIdx.x;                              // 256
    float acc = dwb[ch];
    #pragma unroll
    for (int ky = 0; ky < 3; ky++){
        int yy = y + ky - 1;
        if (yy < 0 || yy > 63) continue;
        #pragma unroll
        for (int kx = 0; kx < 3; kx++){
            int xx = x + kx - 1;
            if (xx < 0 || xx > 63) continue;
            acc = fmaf(dww[ch*9 + ky*3 + kx],
                       g_h1[(size_t)((b<<12) + (yy<<6) + xx)*256 + ch], acc);
        }
    }
    g_g[(size_t)blk*256 + ch] = 0.5f*acc*(1.f + erff(acc*0.70710678118654752f));
}

// ------------------------- host launch -------------------------
extern "C" void kernel_launch(void* const* d_in, const int* in_sizes, int n_in,
                              void* d_out, int out_size){
    const float* x        = (const float*)d_in[0];
    const float* conv1_w  = (const float*)d_in[1];
    const float* conv1_b  = (const float*)d_in[2];
    const float* conv2_w  = (const float*)d_in[3];
    const float* conv2_b  = (const float*)d_in[4];
    const float* ln1_w    = (const float*)d_in[5];
    const float* ln1_b    = (const float*)d_in[6];
    const float* ln2_w    = (const float*)d_in[7];
    const float* ln2_b    = (const float*)d_in[8];
    const float* in_proj  = (const float*)d_in[9];
    const float* c1d_w    = (const float*)d_in[10];
    const float* c1d_b    = (const float*)d_in[11];
    const float* xproj_w  = (const float*)d_in[12];
    const float* dtp_w    = (const float*)d_in[13];
    const float* dtp_b    = (const float*)d_in[14];
    const float* A_log    = (const float*)d_in[15];
    const float* D_param  = (const float*)d_in[16];
    const float* outp_w   = (const float*)d_in[17];
    const float* fc1_w    = (const float*)d_in[18];
    const float* fc1_b    = (const float*)d_in[19];
    const float* dw_w     = (const float*)d_in[20];
    const float* dw_b     = (const float*)d_in[21];
    const float* fc2_w    = (const float*)d_in[22];
    const float* fc2_b    = (const float*)d_in[23];
    float* out = (float*)d_out;

    float *p_t, *p_xz, *p_xc, *p_dbl, *p_yg, *p_h1, *p_g, *p_c1, *p_w1t, *p_w2t;
    cudaGetSymbolAddress((void**)&p_t,   g_t);
    cudaGetSymbolAddress((void**)&p_xz,  g_xz);
    cudaGetSymbolAddress((void**)&p_xc,  g_xc);
    cudaGetSymbolAddress((void**)&p_dbl, g_dbl);
    cudaGetSymbolAddress((void**)&p_yg,  g_yg);
    cudaGetSymbolAddress((void**)&p_h1,  g_h1);
    cudaGetSymbolAddress((void**)&p_g,   g_g);
    cudaGetSymbolAddress((void**)&p_c1,  g_c1);
    cudaGetSymbolAddress((void**)&p_w1t, g_w1t);
    cudaGetSymbolAddress((void**)&p_w2t, g_w2t);

    prep_kernel<<<(KCONV*CC + 255)/256, 256>>>(conv1_w, conv2_w);

    conv3_kernel<0><<<BB*HH, 256>>>(x,    p_w1t, conv1_b);
    conv3_kernel<1><<<BB*HH, 256>>>(p_c1, p_w2t, conv2_b);

    // mamba branch (LN fused into in_proj GEMM)
    gemmln_kernel<0><<<dim3(MM/64, 4), 256>>>(p_t, in_proj, ln1_w, ln1_b, nullptr,
                                              p_xz, 256);
    conv1d_kernel<<<MM*DIN/256, 256>>>(c1d_w, c1d_b);
    gemm_kernel<EPI_STORE><<<dim3(MM/64, 3), 256>>>(p_xc, xproj_w, nullptr, p_dbl,
                                                    MM, 132, 128, nullptr, nullptr);
    dtrepack_kernel<<<MM, 128>>>(dtp_w, dtp_b);

    scan1_kernel<<<dim3(16, NCH, BB), 256>>>(A_log);
    scan2_kernel<<<64, 128>>>();
    scan3_kernel<<<dim3(16, NCH, BB), 256>>>(A_log, D_param);

    gemm_kernel<EPI_ADD><<<dim3(MM/64, 1), 256>>>(p_yg, outp_w, nullptr, p_t,
                                                  MM, 64, 128, nullptr, nullptr);

    // FFN branch (LN fused into fc1 GEMM)
    gemmln_kernel<1><<<dim3(MM/64, 4), 256>>>(p_t, fc1_w, ln2_w, ln2_b, fc1_b,
                                              p_h1, 256);
    dwconv_kernel<<<MM, 256>>>(dw_w, dw_b);
    gemm_kernel<EPI_FINAL><<<dim3(MM/64, 1), 256>>>(p_g, fc2_w, fc2_b, out,
                                                    MM, 64, 256, x, p_t);
}